// round 3
// baseline (speedup 1.0000x reference)
#include <cuda_runtime.h>

// ConvSquare: out = conv3x3(x * f(alpha), w) + bias,  f(t) = (a*t + b)*t + c
// B=4, C=64, O=64, H=W=128, K=3, pad=1.
//
// The spatially-varying kernel depends only on the SOURCE pixel, so this is a
// plain 3x3 conv on y = x * f(alpha), with the premultiply fused into the
// smem tile load.
//
// R2: issue-density redesign.
//  - fma.rn.f32x2 packed FMA (2 MACs / instruction, sm_10x only)
//  - 2x4 pixel block per thread: weight-LDS amortized over 8 pixels
//  - weights duplicated in smem as (w,w) float2 -> one broadcast LDS.64
//    yields the packed b-operand

#define BATCH 4
#define CHN   64
#define OCH   64
#define HH    128
#define WW    128

#define TH 32          // tile rows
#define TW 64          // tile cols
#define OG 8           // output channels per CTA
#define CC 4           // input-channel chunk in smem
#define HALO_H 34      // TH + 2
#define HALO_W 66      // TW + 2
#define XP 68          // smem pitch (mult of 4 -> float4-aligned rows)

#define W2_FLOATS (OG * CHN * 9 * 2)       // 9216  (duplicated pairs)
#define FK_FLOATS (HALO_H * XP)            // 2312
#define XS_FLOATS (CC * HALO_H * XP)       // 9248
#define SMEM_FLOATS (W2_FLOATS + FK_FLOATS + XS_FLOATS)
#define SMEM_BYTES (SMEM_FLOATS * 4)       // 83104 -> 2 CTAs/SM

typedef unsigned long long u64;

__device__ __forceinline__ u64 pack2(float lo, float hi) {
    u64 r;
    asm("mov.b64 %0, {%1, %2};" : "=l"(r) : "f"(lo), "f"(hi));
    return r;
}
__device__ __forceinline__ void unpack2(u64 v, float& lo, float& hi) {
    asm("mov.b64 {%0, %1}, %2;" : "=f"(lo), "=f"(hi) : "l"(v));
}
__device__ __forceinline__ void ffma2(u64& d, u64 a, u64 b) {
    asm("fma.rn.f32x2 %0, %1, %2, %0;" : "+l"(d) : "l"(a), "l"(b));
}

__global__ __launch_bounds__(256, 2)
void conv_sq_kernel(const float* __restrict__ x,
                    const float* __restrict__ alpha,
                    const float* __restrict__ wgt,
                    const float* __restrict__ bias,
                    const float* __restrict__ pa,
                    const float* __restrict__ pb,
                    const float* __restrict__ pc,
                    float* __restrict__ out)
{
    extern __shared__ float smem[];
    float* w2_s = smem;                       // [OG][CHN][9] duplicated float2
    float* fk_s = w2_s + W2_FLOATS;           // [HALO_H][XP]  f(alpha)
    float* x_s  = fk_s + FK_FLOATS;           // [CC][HALO_H][XP] premultiplied

    const int tid = threadIdx.x;
    const int bz  = blockIdx.z;
    const int b   = bz >> 3;                  // batch
    const int og  = bz & 7;                   // o-group of 8
    const int gy0 = blockIdx.y * TH;
    const int gx0 = blockIdx.x * TW;
    const int y0  = gy0 - 1;
    const int x0  = gx0 - 1;

    // ---- weights: duplicate each scalar into a (w,w) float2 in smem
    {
        const float* wg = wgt + og * (OG * CHN * 9);
        #pragma unroll 1
        for (int i = tid; i < OG * CHN * 9; i += 256) {
            float v = __ldg(wg + i);
            ((float2*)w2_s)[i] = make_float2(v, v);
        }
    }

    // ---- f(alpha) halo tile (reused by all 64 input channels)
    {
        const float A = __ldg(pa), Bq = __ldg(pb), Cq = __ldg(pc);
        const float* ap = alpha + b * HH * WW;
        #pragma unroll 1
        for (int i = tid; i < HALO_H * HALO_W; i += 256) {
            int r  = i / HALO_W;
            int cl = i - r * HALO_W;
            int gy = y0 + r, gx = x0 + cl;
            float v = 0.0f;
            if ((unsigned)gy < HH && (unsigned)gx < WW) {
                float t = __ldg(ap + gy * WW + gx);
                v = (A * t + Bq) * t + Cq;
            }
            fk_s[r * XP + cl] = v;
        }
    }

    // thread -> 2 rows x 4 cols pixel block
    const int ty  = tid >> 4;       // 0..15
    const int tx  = tid & 15;       // 0..15
    const int py0 = 2 * ty;
    const int px0 = 4 * tx;

    u64 acc[OG][2][2];              // [o][row][col-pair]
    #pragma unroll
    for (int o = 0; o < OG; o++)
        #pragma unroll
        for (int r = 0; r < 2; r++)
            #pragma unroll
            for (int p = 0; p < 2; p++) acc[o][r][p] = 0ull;

    #pragma unroll 1
    for (int cc0 = 0; cc0 < CHN; cc0 += CC) {
        __syncthreads();            // protect x_s from previous chunk's readers

        #pragma unroll 1
        for (int ci = 0; ci < CC; ci++) {
            const float* xp = x + ((b * CHN + cc0 + ci) * HH) * WW;
            float* xd = x_s + ci * (HALO_H * XP);
            #pragma unroll 1
            for (int i = tid; i < HALO_H * HALO_W; i += 256) {
                int r  = i / HALO_W;
                int cl = i - r * HALO_W;
                int gy = y0 + r, gx = x0 + cl;
                float v = 0.0f;
                if ((unsigned)gy < HH && (unsigned)gx < WW)
                    v = __ldg(xp + gy * WW + gx);
                xd[r * XP + cl] = v * fk_s[r * XP + cl];
            }
        }
        __syncthreads();

        #pragma unroll 1
        for (int ci = 0; ci < CC; ci++) {
            const float* xb = x_s + ci * (HALO_H * XP) + py0 * XP + px0;

            // 4 halo rows, 6 floats each: float4 + float2, then pair them.
            u64 pe[4][3];   // even pairs (0,1) (2,3) (4,5)
            u64 po[4][2];   // odd pairs  (1,2) (3,4)
            #pragma unroll
            for (int r = 0; r < 4; r++) {
                float4 q  = *(const float4*)(xb + r * XP);
                float2 s2 = *(const float2*)(xb + r * XP + 4);
                pe[r][0] = pack2(q.x, q.y);
                pe[r][1] = pack2(q.z, q.w);
                pe[r][2] = pack2(s2.x, s2.y);
                po[r][0] = pack2(q.y, q.z);
                po[r][1] = pack2(q.w, s2.x);
            }

            #pragma unroll
            for (int o = 0; o < OG; o++) {
                const float* wo = w2_s + ((o * CHN + cc0 + ci) * 9) * 2;
                #pragma unroll
                for (int k = 0; k < 3; k++) {
                    #pragma unroll
                    for (int l = 0; l < 3; l++) {
                        u64 wv = *(const u64*)(wo + (k * 3 + l) * 2); // broadcast LDS.64
                        u64 a00 = (l == 0) ? pe[k][0]     : (l == 1) ? po[k][0]     : pe[k][1];
                        u64 a01 = (l == 0) ? pe[k][1]     : (l == 1) ? po[k][1]     : pe[k][2];
                        u64 a10 = (l == 0) ? pe[k + 1][0] : (l == 1) ? po[k + 1][0] : pe[k + 1][1];
                        u64 a11 = (l == 0) ? pe[k + 1][1] : (l == 1) ? po[k + 1][1] : pe[k + 1][2];
                        ffma2(acc[o][0][0], a00, wv);
                        ffma2(acc[o][0][1], a01, wv);
                        ffma2(acc[o][1][0], a10, wv);
                        ffma2(acc[o][1][1], a11, wv);
                    }
                }
            }
        }
    }

    // ---- epilogue
    const int gy = gy0 + py0;
    const int gx = gx0 + px0;
    #pragma unroll
    for (int o = 0; o < OG; o++) {
        float bo = __ldg(bias + og * OG + o);
        float* op = out + (((b * OCH) + og * OG + o) * HH + gy) * WW + gx;
        float c0, c1, c2, c3;
        unpack2(acc[o][0][0], c0, c1);
        unpack2(acc[o][0][1], c2, c3);
        *(float4*)op = make_float4(c0 + bo, c1 + bo, c2 + bo, c3 + bo);
        unpack2(acc[o][1][0], c0, c1);
        unpack2(acc[o][1][1], c2, c3);
        *(float4*)(op + WW) = make_float4(c0 + bo, c1 + bo, c2 + bo, c3 + bo);
    }
}

extern "C" void kernel_launch(void* const* d_in, const int* in_sizes, int n_in,
                              void* d_out, int out_size)
{
    const float* x     = (const float*)d_in[0];
    const float* alpha = (const float*)d_in[1];
    const float* wgt   = (const float*)d_in[2];
    const float* bias  = (const float*)d_in[3];
    const float* pa    = (const float*)d_in[4];
    const float* pb    = (const float*)d_in[5];
    const float* pc    = (const float*)d_in[6];
    float* out = (float*)d_out;

    cudaFuncSetAttribute(conv_sq_kernel,
                         cudaFuncAttributeMaxDynamicSharedMemorySize, SMEM_BYTES);

    dim3 grid(WW / TW, HH / TH, BATCH * (OCH / OG));   // 2 x 4 x 32
    dim3 block(256);
    conv_sq_kernel<<<grid, block, SMEM_BYTES>>>(x, alpha, wgt, bias, pa, pb, pc, out);
}

// round 5
// speedup vs baseline: 4.1183x; 4.1183x over previous
#include <cuda_runtime.h>
#include <cstdint>

#define HH 128
#define WW 128
#define CHN 64
#define OCH 64
#define BATCH 4

#define YP 136          // y smem pitch (floats); 136 % 32 == 8 -> conflict-free gather
#define WP 72           // w smem pitch (floats); 72 % 32 == 8

#define Y_FLOATS  (4 * 32 * YP)                 // 17408
#define W_FLOATS  (2 * 32 * WP)                 // 4608 (double buffer)
#define FA_FLOATS (4 * YP)                      // 544
#define OFF_Y  0
#define OFF_W  (OFF_Y + Y_FLOATS)
#define OFF_FA (OFF_W + W_FLOATS)
#define OFF_BI (OFF_FA + FA_FLOATS)
#define SMEM_FLOATS (OFF_BI + 64)
#define SMEM_BYTES  (SMEM_FLOATS * 4)           // ~90.6 KB -> 2 CTAs/SM

__device__ __forceinline__ float to_tf32(float x) {
    float r; asm("cvt.rn.tf32.f32 %0, %1;" : "=f"(r) : "f"(x)); return r;
}

__device__ __forceinline__ void mma_tf32(float* d, const uint32_t* a, const uint32_t* b) {
    asm volatile(
        "mma.sync.aligned.m16n8k8.row.col.f32.tf32.tf32.f32 "
        "{%0,%1,%2,%3}, {%4,%5,%6,%7}, {%8,%9}, {%0,%1,%2,%3};\n"
        : "+f"(d[0]), "+f"(d[1]), "+f"(d[2]), "+f"(d[3])
        : "r"(a[0]), "r"(a[1]), "r"(a[2]), "r"(a[3]), "r"(b[0]), "r"(b[1]));
}

// ---- prepacked weights: g_wt[h][tap][c(32)][WP], value = tf32(W[o=n][h*32+c][tap])
__device__ float g_wt[2 * 9 * 32 * WP];

__global__ void wt_prepack(const float* __restrict__ w) {
    int i = blockIdx.x * 256 + threadIdx.x;
    if (i >= 2 * 9 * 32 * 64) return;
    int n = i & 63;
    int c = (i >> 6) & 31;
    int ht = i >> 11;          // h*9 + t
    int t = ht % 9;
    int h = ht / 9;
    float v = w[(n * CHN + h * 32 + c) * 9 + t];
    g_wt[((h * 9 + t) * 32 + c) * WP + n] = to_tf32(v);
}

// ============================ main kernel ============================
// CTA = (batch, row-pair). M = 256 pixels (2 rows x 128), N = 64, K = 576.
// 8 warps; warp tile 32(px) x 64(o) = 2 m16-tiles x 8 n8-tiles.

__global__ __launch_bounds__(256, 2)
void conv_mma(const float* __restrict__ x,
              const float* __restrict__ alpha,
              const float* __restrict__ bias,
              const float* __restrict__ pa,
              const float* __restrict__ pb,
              const float* __restrict__ pc,
              float* __restrict__ out)
{
    extern __shared__ float sm[];
    float* y_s  = sm + OFF_Y;    // [4 imgrows][32 c][YP]
    float* w_s  = sm + OFF_W;    // [2 bufs][32 c][WP]
    float* fa_s = sm + OFF_FA;   // [4 imgrows][YP]
    float* bi_s = sm + OFF_BI;   // [64]

    const int tid  = threadIdx.x;
    const int warp = tid >> 5;
    const int lane = tid & 31;
    const int qid  = lane >> 2;  // 0..7
    const int tq   = lane & 3;   // 0..3

    const int rp = blockIdx.x;   // row pair 0..63
    const int b  = blockIdx.y;   // batch
    const int r0 = 2 * rp;

    const int lr  = warp >> 2;          // which of the 2 output rows
    const int px0 = (warp & 3) * 32;    // pixel block start

    // ---- f(alpha) for imgrows r0-1 .. r0+2, padded (col j -> image col j-1)
    {
        const float A = __ldg(pa), Bq = __ldg(pb), Cq = __ldg(pc);
        const float* ap = alpha + b * HH * WW;
        for (int i = tid; i < 4 * YP; i += 256) {
            int ir = i / YP, j = i - ir * YP;
            int gy = r0 - 1 + ir, gx = j - 1;
            float v = 0.0f;
            if ((unsigned)gy < HH && (unsigned)gx < WW) {
                float t = __ldg(ap + gy * WW + gx);
                v = (A * t + Bq) * t + Cq;
            }
            fa_s[i] = v;
        }
    }
    if (tid < 64) bi_s[tid] = __ldg(bias + tid);

    // ---- preload weight buffer for g=0
    {
        const float4* src = (const float4*)g_wt;
        float4* dst = (float4*)w_s;
        for (int i = tid; i < (32 * WP) / 4; i += 256) dst[i] = src[i];
    }

    float d[2][8][4];
    #pragma unroll
    for (int mi = 0; mi < 2; mi++)
        #pragma unroll
        for (int j = 0; j < 8; j++)
            #pragma unroll
            for (int r = 0; r < 4; r++) d[mi][j][r] = 0.0f;

    // per-thread fragment bases
    const int abase = (lr * 32 + tq) * YP + px0 + qid;   // + kt*32*YP + lt + cq*8*YP + mi*16
    const int bbase = tq * WP + qid;                     // + buf*32*WP + cq*8*WP + j*8

    int g = 0;
    #pragma unroll 1
    for (int h = 0; h < 2; h++) {
        __syncthreads();
        // ---- y half: premultiplied + tf32-rounded, rows r0-1..r0+2, 32 channels
        #pragma unroll 1
        for (int e = tid; e < 4 * 32 * 128; e += 256) {
            int px = e & 127;
            int c  = (e >> 7) & 31;
            int ir = e >> 12;
            int gy = r0 - 1 + ir;
            float v = 0.0f;
            if ((unsigned)gy < HH)
                v = __ldg(x + (((b * CHN + h * 32 + c) * HH) + gy) * WW + px);
            y_s[(ir * 32 + c) * YP + 1 + px] = to_tf32(v * fa_s[ir * YP + 1 + px]);
        }
        if (tid < 128) {            // zero pad left/right columns for all 128 (ir,c) rows
            y_s[tid * YP + 0]   = 0.0f;
            y_s[tid * YP + 129] = 0.0f;
        }
        __syncthreads();

        #pragma unroll 1
        for (int t = 0; t < 9; t++) {
            // prefetch next tap's weights into the other buffer
            if (g < 17) {
                const float4* src = (const float4*)(g_wt + (g + 1) * (32 * WP));
                float4* dst = (float4*)(w_s + ((g + 1) & 1) * (32 * WP));
                #pragma unroll 3
                for (int i = tid; i < (32 * WP) / 4; i += 256) dst[i] = src[i];
            }

            const int kt = t / 3, lt = t - 3 * kt;
            const float* ya = y_s + abase + kt * (32 * YP) + lt;
            const float* wb = w_s + bbase + (g & 1) * (32 * WP);

            #pragma unroll
            for (int cq = 0; cq < 4; cq++) {
                const float* yq = ya + cq * (8 * YP);
                const float* wq = wb + cq * (8 * WP);

                uint32_t a[2][4];
                #pragma unroll
                for (int mi = 0; mi < 2; mi++) {
                    const float* p = yq + mi * 16;
                    a[mi][0] = __float_as_uint(p[0]);           // (row,   col)
                    a[mi][1] = __float_as_uint(p[8]);           // (row+8, col)
                    a[mi][2] = __float_as_uint(p[4 * YP]);      // (row,   col+4)
                    a[mi][3] = __float_as_uint(p[4 * YP + 8]);  // (row+8, col+4)
                }
                uint32_t bf[8][2];
                #pragma unroll
                for (int j = 0; j < 8; j++) {
                    bf[j][0] = __float_as_uint(wq[j * 8]);            // (k,   n)
                    bf[j][1] = __float_as_uint(wq[4 * WP + j * 8]);   // (k+4, n)
                }
                #pragma unroll
                for (int mi = 0; mi < 2; mi++)
                    #pragma unroll
                    for (int j = 0; j < 8; j++)
                        mma_tf32(d[mi][j], a[mi], bf[j]);
            }
            __syncthreads();
            g++;
        }
    }

    // ---- epilogue: C frag c0,c1 = (row=qid, o=2tq, 2tq+1); c2,c3 = row+8
    const int imgrow = r0 + lr;
    #pragma unroll
    for (int j = 0; j < 8; j++) {
        const int o0 = j * 8 + 2 * tq;
        const float b0v = bi_s[o0], b1v = bi_s[o0 + 1];
        float* p0 = out + (((b * OCH + o0) * HH) + imgrow) * WW;
        #pragma unroll
        for (int mi = 0; mi < 2; mi++) {
            const int px = px0 + mi * 16 + qid;
            p0[px]               = d[mi][j][0] + b0v;
            p0[HH * WW + px]     = d[mi][j][1] + b1v;
            p0[px + 8]           = d[mi][j][2] + b0v;
            p0[HH * WW + px + 8] = d[mi][j][3] + b1v;
        }
    }
}

// ============================ launch ============================
extern "C" void kernel_launch(void* const* d_in, const int* in_sizes, int n_in,
                              void* d_out, int out_size)
{
    const float* x     = (const float*)d_in[0];
    const float* alpha = (const float*)d_in[1];
    const float* wgt   = (const float*)d_in[2];
    const float* bias  = (const float*)d_in[3];
    const float* pa    = (const float*)d_in[4];
    const float* pb    = (const float*)d_in[5];
    const float* pc    = (const float*)d_in[6];
    float* out = (float*)d_out;

    wt_prepack<<<(2 * 9 * 32 * 64 + 255) / 256, 256>>>(wgt);

    cudaFuncSetAttribute(conv_mma,
                         cudaFuncAttributeMaxDynamicSharedMemorySize, SMEM_BYTES);
    dim3 grid(HH / 2, BATCH);   // 64 row-pairs x 4 batches = 256 CTAs, single wave
    conv_mma<<<grid, 256, SMEM_BYTES>>>(x, alpha, bias, pa, pb, pc, out);
}